// round 15
// baseline (speedup 1.0000x reference)
#include <cuda_runtime.h>
#include <stddef.h>
#include <stdint.h>

// Problem constants
#define C_CH   32
#define NROW   1024
#define D_DIM  768
#define BHALF  512
#define RSTRIDE (32 * 768)   // float stride between consecutive batch rows of a channel

// ---- scratch (device globals; no allocation allowed) ----
__device__ float  g_sq[C_CH * NROW];
__device__ float  g_colpart[C_CH * 8 * D_DIM];
__device__ float  g_negc[C_CH];
__device__ double g_acc[C_CH * 3];   // per channel: Sxx, Syy, (Sxy+Syx)

__device__ __forceinline__ const float* row_base(const float* __restrict__ src,
                                                 const float* __restrict__ tgt,
                                                 int c, int i) {
    return (i < BHALF)
        ? src + ((size_t)i * 32 + c) * 768
        : tgt + ((size_t)(i - BHALF) * 32 + c) * 768;
}

// exp2 on the FMA pipe: valid for |x| < 2^22, here x in (-1, +eps]
__device__ __forceinline__ float fast_exp2(float x) {
    float r = x + 12582912.0f;
    int   n = __float_as_int(r);
    float f = x - (r - 12582912.0f);
    float p = 1.5403530e-4f;
    p = fmaf(p, f, 1.3333558e-3f);
    p = fmaf(p, f, 9.6181291e-3f);
    p = fmaf(p, f, 5.5504109e-2f);
    p = fmaf(p, f, 2.4022651e-1f);
    p = fmaf(p, f, 6.9314718e-1f);
    p = fmaf(p, f, 1.0f);
    return __int_as_float(__float_as_int(p) + (n << 23));
}

// split 2 floats -> fp16 hi half2 + fp16 lo half2 (hi = 10-bit trunc, exactly fp16; lo exact residual)
__device__ __forceinline__ void split2(float x, float y, uint32_t& h2, uint32_t& l2) {
    float h0 = __uint_as_float(__float_as_uint(x) & 0xFFFFE000u);
    float h1 = __uint_as_float(__float_as_uint(y) & 0xFFFFE000u);
    float l0 = x - h0;
    float l1 = y - h1;
    asm("cvt.rn.f16x2.f32 %0, %1, %2;" : "=r"(h2) : "f"(h1), "f"(h0));  // low half = x
    asm("cvt.rn.f16x2.f32 %0, %1, %2;" : "=r"(l2) : "f"(l1), "f"(l0));
}

// ---- P1: per-row squared norms (one warp per row) ----
__global__ void psq_kernel(const float* __restrict__ src, const float* __restrict__ tgt) {
    int c    = blockIdx.x;
    int warp = threadIdx.x >> 5, lane = threadIdx.x & 31;
    int i    = blockIdx.y * 8 + warp;
    const float4* rp = (const float4*)row_base(src, tgt, c, i);
    float s = 0.f;
#pragma unroll
    for (int j = 0; j < 6; ++j) {
        float4 v = rp[lane + 32 * j];
        s += v.x * v.x + v.y * v.y + v.z * v.z + v.w * v.w;
    }
#pragma unroll
    for (int off = 16; off; off >>= 1) s += __shfl_down_sync(0xffffffffu, s, off);
    if (lane == 0) g_sq[c * NROW + i] = s;
}

// ---- P2: partial column sums (for bandwidth) ----
__global__ void pcol_kernel(const float* __restrict__ src, const float* __restrict__ tgt) {
    int c = blockIdx.x, part = blockIdx.y;
    int t = threadIdx.x;
    float4 s = make_float4(0.f, 0.f, 0.f, 0.f);
    for (int r = 0; r < 128; ++r) {
        const float4* rp = (const float4*)row_base(src, tgt, c, part * 128 + r);
        float4 v = rp[t];
        s.x += v.x; s.y += v.y; s.z += v.z; s.w += v.w;
    }
    ((float4*)g_colpart)[(c * 8 + part) * 192 + t] = s;
}

// ---- P3: bandwidth coefficient per channel + zero accumulators ----
__global__ void pband_kernel() {
    int c = blockIdx.x, tid = threadIdx.x;
    __shared__ double sh[256];
    double acc = 0.0;
    for (int i = tid; i < NROW; i += 256)
        acc += 2.0 * (double)NROW * (double)g_sq[c * NROW + i];
    for (int d = tid; d < D_DIM; d += 256) {
        float cs = 0.f;
#pragma unroll
        for (int p = 0; p < 8; ++p) cs += g_colpart[(c * 8 + p) * D_DIM + d];
        acc -= 2.0 * (double)cs * (double)cs;
    }
    sh[tid] = acc;
    __syncthreads();
    for (int s = 128; s > 0; s >>= 1) {
        if (tid < s) sh[tid] += sh[tid + s];
        __syncthreads();
    }
    if (tid == 0) {
        double sumd2 = sh[0];
        double bw0 = sumd2 / ((double)NROW * NROW - NROW) / 4.0;
        double bw4 = bw0 * 16.0;
        g_negc[c] = (float)(-1.4426950408889634 / bw4);
        g_acc[c * 3 + 0] = 0.0;
        g_acc[c * 3 + 1] = 0.0;
        g_acc[c * 3 + 2] = 0.0;
    }
}

// ============ main kernel: fp16x3 mma.sync m16n8k16 GEMM + RBF epilogue ============
// Tile 128x128, BK=16 halves/slab (48 slabs). Loader: LDG raw fp32 -> regs (prefetched
// one slab ahead, hidden under MMA), split ONCE per element, STS to double-buffered
// fp16 hi/lo tiles. MMA loop: pure LDS.32 fragment loads + tensor ops, 1 sync/slab.
// dot = hi*hi + hi*lo + lo*hi (bit-identical numerics to R11's in-register split).
#define BM   128
#define BKH  16    // halves (=floats) per slab
#define LDKW 12    // fp16 tile row stride in half2 words (8 data + 4 pad); all-32-bank frags

#define TILE_W   (BM * LDKW)                   // 1536 words
#define STAGE_W  (4 * TILE_W)                  // AH, AL, BH, BL = 6144 words
#define OFF_SQA  (2 * STAGE_W)                 // 12288
#define OFF_SQB  (OFF_SQA + BM)
#define OFF_RED  (OFF_SQB + BM)
#define SMEM_WORDS (OFF_RED + 256)             // 12800
#define SMEM_BYTES (SMEM_WORDS * 4)            // 51200

__device__ __forceinline__ void mma_f16(float& c0, float& c1, float& c2, float& c3,
                                        uint32_t a0, uint32_t a1, uint32_t a2, uint32_t a3,
                                        uint32_t b0, uint32_t b1) {
    asm volatile("mma.sync.aligned.m16n8k16.row.col.f32.f16.f16.f32 "
                 "{%0,%1,%2,%3}, {%4,%5,%6,%7}, {%8,%9}, {%0,%1,%2,%3};"
                 : "+f"(c0), "+f"(c1), "+f"(c2), "+f"(c3)
                 : "r"(a0), "r"(a1), "r"(a2), "r"(a3), "r"(b0), "r"(b1));
}

__global__ __launch_bounds__(256, 2) void mmd_gemm_kernel(const float* __restrict__ src,
                                                          const float* __restrict__ tgt) {
    extern __shared__ uint32_t smw[];
    float* sqa_sm = (float*)(smw + OFF_SQA);
    float* sqb_sm = (float*)(smw + OFF_SQB);
    float* red    = (float*)(smw + OFF_RED);

    const int c = blockIdx.y;

    // tile index -> upper-triangular (bi, bj), bi <= bj
    int bi = 0, rem = blockIdx.x;
    while (rem >= (8 - bi)) { rem -= (8 - bi); ++bi; }
    const int bj = bi + rem;
    const int i0 = bi * BM, j0 = bj * BM;

    const int tid  = threadIdx.x;
    const int wid  = tid >> 5, lane = tid & 31;
    const int g    = lane >> 2;       // groupID (0..7)
    const int tig  = lane & 3;        // thread-in-group (0..3)
    const int wm0  = (wid >> 2) * 64;
    const int wn0  = (wid & 3) * 32;

    if (tid < 128) sqa_sm[tid] = g_sq[c * NROW + i0 + tid];
    else           sqb_sm[tid - 128] = g_sq[c * NROW + j0 + (tid - 128)];

    // loader mapping: 2 threads per tile row; thread owns floats [lkv*8, lkv*8+8)
    const int lrow = tid >> 1;        // 0..127
    const int lkv  = tid & 1;         // 0..1
    const float* pA = row_base(src, tgt, c, i0) + (size_t)lrow * RSTRIDE + lkv * 8;
    const float* pB = row_base(src, tgt, c, j0) + (size_t)lrow * RSTRIDE + lkv * 8;
    const int tw = lrow * LDKW + lkv * 4;   // tile word offset for this thread's uint4

    float cacc[4][4][4];
#pragma unroll
    for (int ma = 0; ma < 4; ++ma)
#pragma unroll
        for (int na = 0; na < 4; ++na)
#pragma unroll
            for (int q = 0; q < 4; ++q) cacc[ma][na][q] = 0.f;

    const int NK = D_DIM / BKH;   // 48

    // prefetch slab 0 raw into registers
    float4 ra0 = *(const float4*)(pA);
    float4 ra1 = *(const float4*)(pA + 4);
    float4 rb0 = *(const float4*)(pB);
    float4 rb1 = *(const float4*)(pB + 4);

    for (int ks = 0; ks < NK; ++ks) {
        const int s = ks & 1;
        uint32_t* AH = smw + s * STAGE_W + 0 * TILE_W;
        uint32_t* AL = smw + s * STAGE_W + 1 * TILE_W;
        uint32_t* BH = smw + s * STAGE_W + 2 * TILE_W;
        uint32_t* BL = smw + s * STAGE_W + 3 * TILE_W;

        // ---- split regs (slab ks) once per element, store fp16 tiles ----
        {
            uint32_t h0, l0, h1, l1, h2, l2, h3, l3;
            split2(ra0.x, ra0.y, h0, l0); split2(ra0.z, ra0.w, h1, l1);
            split2(ra1.x, ra1.y, h2, l2); split2(ra1.z, ra1.w, h3, l3);
            *(uint4*)&AH[tw] = make_uint4(h0, h1, h2, h3);
            *(uint4*)&AL[tw] = make_uint4(l0, l1, l2, l3);
            split2(rb0.x, rb0.y, h0, l0); split2(rb0.z, rb0.w, h1, l1);
            split2(rb1.x, rb1.y, h2, l2); split2(rb1.z, rb1.w, h3, l3);
            *(uint4*)&BH[tw] = make_uint4(h0, h1, h2, h3);
            *(uint4*)&BL[tw] = make_uint4(l0, l1, l2, l3);
        }
        __syncthreads();   // tiles (ks) ready; also fences reuse of stage s from ks-2

        // prefetch slab ks+1 raw (latency hidden under MMA below)
        if (ks + 1 < NK) {
            const int k0 = (ks + 1) * BKH;
            ra0 = *(const float4*)(pA + k0);
            ra1 = *(const float4*)(pA + k0 + 4);
            rb0 = *(const float4*)(pB + k0);
            rb1 = *(const float4*)(pB + k0 + 4);
        }

        // ---- MMA: one K=16 step; pure LDS.32 + tensor ops ----
        uint32_t ah[4][4], al[4][4];
#pragma unroll
        for (int ma = 0; ma < 4; ++ma) {
            const int base = (wm0 + ma * 16 + g) * LDKW + tig;
            ah[ma][0] = AH[base];            al[ma][0] = AL[base];
            ah[ma][1] = AH[base + 8 * LDKW]; al[ma][1] = AL[base + 8 * LDKW];
            ah[ma][2] = AH[base + 4];        al[ma][2] = AL[base + 4];
            ah[ma][3] = AH[base + 8 * LDKW + 4];
            al[ma][3] = AL[base + 8 * LDKW + 4];
        }
#pragma unroll
        for (int na = 0; na < 4; ++na) {
            const int bbase = (wn0 + na * 8 + g) * LDKW + tig;
            const uint32_t bh0 = BH[bbase], bh1 = BH[bbase + 4];
            const uint32_t bl0 = BL[bbase], bl1 = BL[bbase + 4];
#pragma unroll
            for (int ma = 0; ma < 4; ++ma)   // hi x hi
                mma_f16(cacc[ma][na][0], cacc[ma][na][1], cacc[ma][na][2], cacc[ma][na][3],
                        ah[ma][0], ah[ma][1], ah[ma][2], ah[ma][3], bh0, bh1);
#pragma unroll
            for (int ma = 0; ma < 4; ++ma)   // hi x lo
                mma_f16(cacc[ma][na][0], cacc[ma][na][1], cacc[ma][na][2], cacc[ma][na][3],
                        ah[ma][0], ah[ma][1], ah[ma][2], ah[ma][3], bl0, bl1);
#pragma unroll
            for (int ma = 0; ma < 4; ++ma)   // lo x hi
                mma_f16(cacc[ma][na][0], cacc[ma][na][1], cacc[ma][na][2], cacc[ma][na][3],
                        al[ma][0], al[ma][1], al[ma][2], al[ma][3], bh0, bh1);
        }
        // no second sync: next iter writes the OTHER stage; reuse of this stage
        // (iter ks+2) is fenced by iter ks+1's barrier, which each warp reaches
        // only after finishing this MMA phase.
    }

    // ---- epilogue: d2 -> 5-bandwidth RBF sum via one exp2 + 4 squarings ----
    const float negc = g_negc[c];
    float local = 0.f;
#pragma unroll
    for (int ma = 0; ma < 4; ++ma) {
        const float sq_r0 = sqa_sm[wm0 + ma * 16 + g];
        const float sq_r1 = sqa_sm[wm0 + ma * 16 + g + 8];
#pragma unroll
        for (int na = 0; na < 4; ++na) {
            const float sq_c0 = sqb_sm[wn0 + na * 8 + tig * 2];
            const float sq_c1 = sqb_sm[wn0 + na * 8 + tig * 2 + 1];
            float d2v[4];
            d2v[0] = fmaf(-2.0f, cacc[ma][na][0], sq_r0 + sq_c0);
            d2v[1] = fmaf(-2.0f, cacc[ma][na][1], sq_r0 + sq_c1);
            d2v[2] = fmaf(-2.0f, cacc[ma][na][2], sq_r1 + sq_c0);
            d2v[3] = fmaf(-2.0f, cacc[ma][na][3], sq_r1 + sq_c1);
#pragma unroll
            for (int q = 0; q < 4; ++q) {
                float e4 = fast_exp2(d2v[q] * negc);
                float e3 = e4 * e4;
                float e2 = e3 * e3;
                float e1 = e2 * e2;
                float e0 = e1 * e1;
                local += ((e0 + e1) + (e2 + e3)) + e4;
            }
        }
    }

    red[tid] = local;
    __syncthreads();
    for (int s = 128; s > 0; s >>= 1) {
        if (tid < s) red[tid] += red[tid + s];
        __syncthreads();
    }
    if (tid == 0) {
        int region = (bj < 4) ? 0 : ((bi >= 4) ? 1 : 2);   // XX / YY / XY
        double w = (bi == bj) ? 1.0 : 2.0;                 // symmetry weight
        atomicAdd(&g_acc[c * 3 + region], w * (double)red[0]);
    }
}

// ---- finalize: mean over channels of (Sxx + Syy - (Sxy+Syx)) / B^2 ----
__global__ void final_kernel(float* __restrict__ out) {
    int c = threadIdx.x;   // 32 threads
    double mmd = (g_acc[c * 3 + 0] + g_acc[c * 3 + 1] - g_acc[c * 3 + 2])
                 * (1.0 / (512.0 * 512.0));
#pragma unroll
    for (int off = 16; off; off >>= 1)
        mmd += __shfl_down_sync(0xffffffffu, mmd, off);
    if (c == 0) out[0] = (float)(mmd / 32.0);
}

extern "C" void kernel_launch(void* const* d_in, const int* in_sizes, int n_in,
                              void* d_out, int out_size) {
    const float* src = (const float*)d_in[0];
    const float* tgt = (const float*)d_in[1];
    float* out = (float*)d_out;

    cudaFuncSetAttribute(mmd_gemm_kernel, cudaFuncAttributeMaxDynamicSharedMemorySize, SMEM_BYTES);

    psq_kernel<<<dim3(32, 128), 256>>>(src, tgt);
    pcol_kernel<<<dim3(32, 8), 192>>>(src, tgt);
    pband_kernel<<<32, 256>>>();
    mmd_gemm_kernel<<<dim3(36, 32), 256, SMEM_BYTES>>>(src, tgt);
    final_kernel<<<1, 32>>>(out);
}

// round 16
// speedup vs baseline: 1.2771x; 1.2771x over previous
#include <cuda_runtime.h>
#include <stddef.h>
#include <stdint.h>

// Problem constants
#define C_CH   32
#define NROW   1024
#define D_DIM  768
#define BHALF  512
#define RSTRIDE (32 * 768)   // float stride between consecutive batch rows of a channel

// ---- scratch (device globals; no allocation allowed) ----
__device__ float  g_sq[C_CH * NROW];
__device__ float  g_colpart[C_CH * 128 * D_DIM];   // per-block column partials (12.6 MB)
__device__ float  g_negc[C_CH];
__device__ double g_acc[C_CH * 3];   // per channel: Sxx, Syy, (Sxy+Syx)

__device__ __forceinline__ const float* row_base(const float* __restrict__ src,
                                                 const float* __restrict__ tgt,
                                                 int c, int i) {
    return (i < BHALF)
        ? src + ((size_t)i * 32 + c) * 768
        : tgt + ((size_t)(i - BHALF) * 32 + c) * 768;
}

// exp2 on the FMA pipe: valid for |x| < 2^22, here x in (-1, +eps]
__device__ __forceinline__ float fast_exp2(float x) {
    float r = x + 12582912.0f;
    int   n = __float_as_int(r);
    float f = x - (r - 12582912.0f);
    float p = 1.5403530e-4f;
    p = fmaf(p, f, 1.3333558e-3f);
    p = fmaf(p, f, 9.6181291e-3f);
    p = fmaf(p, f, 5.5504109e-2f);
    p = fmaf(p, f, 2.4022651e-1f);
    p = fmaf(p, f, 6.9314718e-1f);
    p = fmaf(p, f, 1.0f);
    return __int_as_float(__float_as_int(p) + (n << 23));
}

__device__ __forceinline__ uint32_t smem_u32(const void* p) {
    uint32_t a;
    asm("{ .reg .u64 t; cvta.to.shared.u64 t, %1; cvt.u32.u64 %0, t; }" : "=r"(a) : "l"(p));
    return a;
}
__device__ __forceinline__ void cp16(uint32_t dst, const void* src) {
    asm volatile("cp.async.cg.shared.global [%0], [%1], 16;" :: "r"(dst), "l"(src));
}
#define CP_COMMIT() asm volatile("cp.async.commit_group;" ::: "memory")
#define CP_WAIT(n)  asm volatile("cp.async.wait_group %0;" :: "n"(n) : "memory")

// ---- P1 (fused): per-row squared norms + per-block column partial sums ----
// Block = (channel c, 8 consecutive rows). One warp per row. Rows staged in smem,
// then 192 threads produce the 768-wide column partial for this block.
__global__ void psq_kernel(const float* __restrict__ src, const float* __restrict__ tgt) {
    __shared__ float4 rowbuf[8][192];   // 24 KB
    int c    = blockIdx.x;
    int by   = blockIdx.y;
    int warp = threadIdx.x >> 5, lane = threadIdx.x & 31;
    int i    = by * 8 + warp;
    const float4* rp = (const float4*)row_base(src, tgt, c, i);
    float s = 0.f;
#pragma unroll
    for (int j = 0; j < 6; ++j) {
        int f = lane + 32 * j;
        float4 v = rp[f];
        s += v.x * v.x + v.y * v.y + v.z * v.z + v.w * v.w;
        rowbuf[warp][f] = v;
    }
#pragma unroll
    for (int off = 16; off; off >>= 1) s += __shfl_down_sync(0xffffffffu, s, off);
    if (lane == 0) g_sq[c * NROW + i] = s;

    __syncthreads();
    int t = threadIdx.x;
    if (t < 192) {
        float4 cs = make_float4(0.f, 0.f, 0.f, 0.f);
#pragma unroll
        for (int w = 0; w < 8; ++w) {
            float4 v = rowbuf[w][t];
            cs.x += v.x; cs.y += v.y; cs.z += v.z; cs.w += v.w;
        }
        ((float4*)g_colpart)[((size_t)c * 128 + by) * 192 + t] = cs;
    }
}

// ---- P3: bandwidth coefficient per channel + zero accumulators ----
// sum(d2) = 2n*sum(sq) - 2*||colsum||^2
__global__ void pband_kernel() {
    int c = blockIdx.x, tid = threadIdx.x;
    __shared__ double sh[256];
    double acc = 0.0;
    for (int i = tid; i < NROW; i += 256)
        acc += 2.0 * (double)NROW * (double)g_sq[c * NROW + i];
    for (int d = tid; d < D_DIM; d += 256) {
        float cs = 0.f;
        for (int p = 0; p < 128; ++p)
            cs += g_colpart[((size_t)c * 128 + p) * D_DIM + d];
        acc -= 2.0 * (double)cs * (double)cs;
    }
    sh[tid] = acc;
    __syncthreads();
    for (int s = 128; s > 0; s >>= 1) {
        if (tid < s) sh[tid] += sh[tid + s];
        __syncthreads();
    }
    if (tid == 0) {
        double sumd2 = sh[0];
        double bw0 = sumd2 / ((double)NROW * NROW - NROW) / 4.0;
        double bw4 = bw0 * 16.0;
        g_negc[c] = (float)(-1.4426950408889634 / bw4);
        g_acc[c * 3 + 0] = 0.0;
        g_acc[c * 3 + 1] = 0.0;
        g_acc[c * 3 + 2] = 0.0;
    }
}

// ============ main kernel: fp16x3 mma.sync m16n8k16 GEMM + RBF epilogue ============
// EXACT R11 structure (best measured: 291.9 us): tile 128x128, BK=32, 2-stage
// cp.async pipeline of RAW fp32 tiles; fp16 hi/lo split at fragment-load time in
// registers. dot = hi*hi + hi*lo + lo*hi. Scheme error ~2^-22.
#define BM   128
#define BK   32
#define LDK  40    // fp32 words/row; float2 frag loads: word (40g + 2tig) conflict-free

// dynamic smem layout (floats)
#define OFF_AS   0
#define OFF_BS   (2 * BM * LDK)            // 10240
#define OFF_SQA  (4 * BM * LDK)            // 20480
#define OFF_SQB  (OFF_SQA + BM)
#define OFF_RED  (OFF_SQB + BM)
#define SMEM_FLOATS (OFF_RED + 256)        // 20992
#define SMEM_BYTES  (SMEM_FLOATS * 4)      // 83968

__device__ __forceinline__ void mma_f16(float& c0, float& c1, float& c2, float& c3,
                                        uint32_t a0, uint32_t a1, uint32_t a2, uint32_t a3,
                                        uint32_t b0, uint32_t b1) {
    asm volatile("mma.sync.aligned.m16n8k16.row.col.f32.f16.f16.f32 "
                 "{%0,%1,%2,%3}, {%4,%5,%6,%7}, {%8,%9}, {%0,%1,%2,%3};"
                 : "+f"(c0), "+f"(c1), "+f"(c2), "+f"(c3)
                 : "r"(a0), "r"(a1), "r"(a2), "r"(a3), "r"(b0), "r"(b1));
}

// split float2 -> fp16 hi half2 + fp16 lo half2.
// hi = f32 masked to 10 mantissa bits (exactly fp16-representable); lo = exact residual.
__device__ __forceinline__ void split2(float2 v, uint32_t& h2, uint32_t& l2) {
    float h0 = __uint_as_float(__float_as_uint(v.x) & 0xFFFFE000u);
    float h1 = __uint_as_float(__float_as_uint(v.y) & 0xFFFFE000u);
    float l0 = v.x - h0;
    float l1 = v.y - h1;
    asm("cvt.rn.f16x2.f32 %0, %1, %2;" : "=r"(h2) : "f"(h1), "f"(h0));  // low half = x
    asm("cvt.rn.f16x2.f32 %0, %1, %2;" : "=r"(l2) : "f"(l1), "f"(l0));
}

__global__ __launch_bounds__(256, 2) void mmd_gemm_kernel(const float* __restrict__ src,
                                                          const float* __restrict__ tgt) {
    extern __shared__ float sm[];
    float* As = sm + OFF_AS;   // [2][BM][LDK] raw fp32
    float* Bs = sm + OFF_BS;
    float* sqa_sm = sm + OFF_SQA;
    float* sqb_sm = sm + OFF_SQB;
    float* red = sm + OFF_RED;

    const int c = blockIdx.y;

    // tile index -> upper-triangular (bi, bj), bi <= bj
    int bi = 0, rem = blockIdx.x;
    while (rem >= (8 - bi)) { rem -= (8 - bi); ++bi; }
    const int bj = bi + rem;
    const int i0 = bi * BM, j0 = bj * BM;

    const int tid  = threadIdx.x;
    const int wid  = tid >> 5, lane = tid & 31;
    const int g    = lane >> 2;       // groupID (0..7)
    const int tig  = lane & 3;        // thread-in-group (0..3)
    const int wm0  = (wid >> 2) * 64;
    const int wn0  = (wid & 3) * 32;

    if (tid < 128) sqa_sm[tid] = g_sq[c * NROW + i0 + tid];
    else           sqb_sm[tid - 128] = g_sq[c * NROW + j0 + (tid - 128)];

    // loader mapping: thread -> (row 0..31, kvec 0..7); covers rows {lrow, +32, +64, +96}
    const int lrow = tid >> 3;
    const int lkv  = tid & 7;
    const float* pA = row_base(src, tgt, c, i0) + (size_t)lrow * RSTRIDE + lkv * 4;
    const float* pB = row_base(src, tgt, c, j0) + (size_t)lrow * RSTRIDE + lkv * 4;

    const uint32_t dA = smem_u32(&As[lrow * LDK + lkv * 4]);
    const uint32_t dB = smem_u32(&Bs[lrow * LDK + lkv * 4]);
    const uint32_t stageB = (uint32_t)(BM * LDK * 4);   // bytes per stage
    const uint32_t rowB   = (uint32_t)(32 * LDK * 4);   // 32 smem rows in bytes
    const size_t   rowG   = (size_t)32 * RSTRIDE;

    float cacc[4][4][4];
#pragma unroll
    for (int ma = 0; ma < 4; ++ma)
#pragma unroll
        for (int na = 0; na < 4; ++na)
#pragma unroll
            for (int q = 0; q < 4; ++q) cacc[ma][na][q] = 0.f;

    const int NK = D_DIM / BK;   // 24

    // preload slab 0 into stage 0
#pragma unroll
    for (int p = 0; p < 4; ++p) {
        cp16(dA + p * rowB, pA + p * rowG);
        cp16(dB + p * rowB, pB + p * rowG);
    }
    CP_COMMIT();

    for (int ks = 0; ks < NK; ++ks) {
        const int s = ks & 1;
        if (ks + 1 < NK) {
            const int k0 = (ks + 1) * BK;
            const uint32_t so = ((ks + 1) & 1) ? stageB : 0u;
#pragma unroll
            for (int p = 0; p < 4; ++p) {
                cp16(dA + so + p * rowB, pA + k0 + p * rowG);
                cp16(dB + so + p * rowB, pB + k0 + p * rowG);
            }
            CP_COMMIT();
            CP_WAIT(1);
        } else {
            CP_WAIT(0);
        }
        __syncthreads();

        const float* Ast = As + s * BM * LDK;
        const float* Bst = Bs + s * BM * LDK;
#pragma unroll
        for (int kk = 0; kk < BK; kk += 16) {
            // fp32 fragment loads (LDS.64) + in-register fp16 hi/lo split
            uint32_t ah[4][4], al[4][4], bh[4][2], bl[4][2];
#pragma unroll
            for (int ma = 0; ma < 4; ++ma) {
                const float* ar = &Ast[(wm0 + ma * 16 + g) * LDK + kk + 2 * tig];
                split2(*(const float2*)(ar),               ah[ma][0], al[ma][0]);  // row g,   k lo
                split2(*(const float2*)(ar + 8 * LDK),     ah[ma][1], al[ma][1]);  // row g+8, k lo
                split2(*(const float2*)(ar + 8),           ah[ma][2], al[ma][2]);  // row g,   k hi
                split2(*(const float2*)(ar + 8 * LDK + 8), ah[ma][3], al[ma][3]);  // row g+8, k hi
            }
#pragma unroll
            for (int na = 0; na < 4; ++na) {
                const float* br = &Bst[(wn0 + na * 8 + g) * LDK + kk + 2 * tig];
                split2(*(const float2*)(br),     bh[na][0], bl[na][0]);            // k lo
                split2(*(const float2*)(br + 8), bh[na][1], bl[na][1]);            // k hi
            }
            // pass 1: hi x hi
#pragma unroll
            for (int ma = 0; ma < 4; ++ma)
#pragma unroll
                for (int na = 0; na < 4; ++na)
                    mma_f16(cacc[ma][na][0], cacc[ma][na][1], cacc[ma][na][2], cacc[ma][na][3],
                            ah[ma][0], ah[ma][1], ah[ma][2], ah[ma][3],
                            bh[na][0], bh[na][1]);
            // pass 2: hi x lo
#pragma unroll
            for (int ma = 0; ma < 4; ++ma)
#pragma unroll
                for (int na = 0; na < 4; ++na)
                    mma_f16(cacc[ma][na][0], cacc[ma][na][1], cacc[ma][na][2], cacc[ma][na][3],
                            ah[ma][0], ah[ma][1], ah[ma][2], ah[ma][3],
                            bl[na][0], bl[na][1]);
            // pass 3: lo x hi
#pragma unroll
            for (int ma = 0; ma < 4; ++ma)
#pragma unroll
                for (int na = 0; na < 4; ++na)
                    mma_f16(cacc[ma][na][0], cacc[ma][na][1], cacc[ma][na][2], cacc[ma][na][3],
                            al[ma][0], al[ma][1], al[ma][2], al[ma][3],
                            bh[na][0], bh[na][1]);
        }
        __syncthreads();
    }

    // ---- epilogue: d2 -> 5-bandwidth RBF sum via one exp2 + 4 squarings ----
    // D-fragment layout: c0=(g,2tig) c1=(g,2tig+1) c2=(g+8,2tig) c3=(g+8,2tig+1)
    const float negc = g_negc[c];
    float local = 0.f;
#pragma unroll
    for (int ma = 0; ma < 4; ++ma) {
        const float sq_r0 = sqa_sm[wm0 + ma * 16 + g];
        const float sq_r1 = sqa_sm[wm0 + ma * 16 + g + 8];
#pragma unroll
        for (int na = 0; na < 4; ++na) {
            const float sq_c0 = sqb_sm[wn0 + na * 8 + tig * 2];
            const float sq_c1 = sqb_sm[wn0 + na * 8 + tig * 2 + 1];
            float d2v[4];
            d2v[0] = fmaf(-2.0f, cacc[ma][na][0], sq_r0 + sq_c0);
            d2v[1] = fmaf(-2.0f, cacc[ma][na][1], sq_r0 + sq_c1);
            d2v[2] = fmaf(-2.0f, cacc[ma][na][2], sq_r1 + sq_c0);
            d2v[3] = fmaf(-2.0f, cacc[ma][na][3], sq_r1 + sq_c1);
#pragma unroll
            for (int q = 0; q < 4; ++q) {
                float e4 = fast_exp2(d2v[q] * negc);
                float e3 = e4 * e4;
                float e2 = e3 * e3;
                float e1 = e2 * e2;
                float e0 = e1 * e1;
                local += ((e0 + e1) + (e2 + e3)) + e4;
            }
        }
    }

    red[tid] = local;
    __syncthreads();
    for (int s = 128; s > 0; s >>= 1) {
        if (tid < s) red[tid] += red[tid + s];
        __syncthreads();
    }
    if (tid == 0) {
        int region = (bj < 4) ? 0 : ((bi >= 4) ? 1 : 2);   // XX / YY / XY
        double w = (bi == bj) ? 1.0 : 2.0;                 // symmetry weight
        atomicAdd(&g_acc[c * 3 + region], w * (double)red[0]);
    }
}

// ---- finalize: mean over channels of (Sxx + Syy - (Sxy+Syx)) / B^2 ----
__global__ void final_kernel(float* __restrict__ out) {
    int c = threadIdx.x;   // 32 threads
    double mmd = (g_acc[c * 3 + 0] + g_acc[c * 3 + 1] - g_acc[c * 3 + 2])
                 * (1.0 / (512.0 * 512.0));
#pragma unroll
    for (int off = 16; off; off >>= 1)
        mmd += __shfl_down_sync(0xffffffffu, mmd, off);
    if (c == 0) out[0] = (float)(mmd / 32.0);
}

extern "C" void kernel_launch(void* const* d_in, const int* in_sizes, int n_in,
                              void* d_out, int out_size) {
    const float* src = (const float*)d_in[0];
    const float* tgt = (const float*)d_in[1];
    float* out = (float*)d_out;

    cudaFuncSetAttribute(mmd_gemm_kernel, cudaFuncAttributeMaxDynamicSharedMemorySize, SMEM_BYTES);

    psq_kernel<<<dim3(32, 128), 256>>>(src, tgt);
    pband_kernel<<<32, 256>>>();
    mmd_gemm_kernel<<<dim3(36, 32), 256, SMEM_BYTES>>>(src, tgt);
    final_kernel<<<1, 32>>>(out);
}